// round 1
// baseline (speedup 1.0000x reference)
#include <cuda_runtime.h>
#include <math.h>

#define S_LEN 8704
#define DIMV  1024
#define NH    16
#define HD    64
#define SD    4608   // dilated stream length (incl. zero padding block)
#define SREAL 4352   // real tokens per stream
#define WIN   512

__device__ float g_q[S_LEN * DIMV];
__device__ float g_k[S_LEN * DIMV];
__device__ float g_v[S_LEN * DIMV];
__device__ float g_o[S_LEN * DIMV];

__device__ __forceinline__ int dil2orig(int d, int p) {
    return ((p >> 8) << 9) + (d << 8) + (p & 255);
}

// ---------------------------------------------------------------------------
// GEMM: C[M,N] = A[M,K] @ B[K,N] + bias[N]   (fp32, 128x128x16, 8x8 microtile)
// M % 128 == 0, N % 128 == 0, K % 16 == 0 (true for all our calls)
// ---------------------------------------------------------------------------
__global__ __launch_bounds__(256) void gemm_bias_kernel(
    const float* __restrict__ A, const float* __restrict__ B,
    const float* __restrict__ bias, float* __restrict__ C,
    int M, int N, int K) {
    __shared__ float As[16][132];
    __shared__ float Bs[16][132];

    const int tid = threadIdx.x;
    const int bm = blockIdx.y << 7;
    const int bn = blockIdx.x << 7;
    const int tx = tid & 15, ty = tid >> 4;

    float acc[8][8];
#pragma unroll
    for (int i = 0; i < 8; i++)
#pragma unroll
        for (int j = 0; j < 8; j++) acc[i][j] = 0.f;

    for (int k0 = 0; k0 < K; k0 += 16) {
        // Stage loads into registers
        float4 a0, a1, b0, b1;
        {
            int idx = tid;
            int r = idx >> 2, c4 = idx & 3;
            a0 = *(const float4*)&A[(size_t)(bm + r) * K + k0 + (c4 << 2)];
            idx = tid + 256;
            r = idx >> 2; c4 = idx & 3;
            a1 = *(const float4*)&A[(size_t)(bm + r) * K + k0 + (c4 << 2)];
            idx = tid;
            r = idx >> 5; c4 = idx & 31;
            b0 = *(const float4*)&B[(size_t)(k0 + r) * N + bn + (c4 << 2)];
            idx = tid + 256;
            r = idx >> 5; c4 = idx & 31;
            b1 = *(const float4*)&B[(size_t)(k0 + r) * N + bn + (c4 << 2)];
        }
        __syncthreads();
        {
            int idx = tid;
            int r = idx >> 2, c4 = idx & 3;
            As[(c4 << 2) + 0][r] = a0.x;
            As[(c4 << 2) + 1][r] = a0.y;
            As[(c4 << 2) + 2][r] = a0.z;
            As[(c4 << 2) + 3][r] = a0.w;
            idx = tid + 256; r = idx >> 2; c4 = idx & 3;
            As[(c4 << 2) + 0][r] = a1.x;
            As[(c4 << 2) + 1][r] = a1.y;
            As[(c4 << 2) + 2][r] = a1.z;
            As[(c4 << 2) + 3][r] = a1.w;
            idx = tid; r = idx >> 5; c4 = idx & 31;
            *(float4*)&Bs[r][c4 << 2] = b0;
            idx = tid + 256; r = idx >> 5; c4 = idx & 31;
            *(float4*)&Bs[r][c4 << 2] = b1;
        }
        __syncthreads();

#pragma unroll
        for (int kk = 0; kk < 16; kk++) {
            float a[8], b[8];
            float4 t;
            t = *(const float4*)&As[kk][ty << 3];       a[0]=t.x; a[1]=t.y; a[2]=t.z; a[3]=t.w;
            t = *(const float4*)&As[kk][(ty << 3) + 4]; a[4]=t.x; a[5]=t.y; a[6]=t.z; a[7]=t.w;
            t = *(const float4*)&Bs[kk][tx << 3];       b[0]=t.x; b[1]=t.y; b[2]=t.z; b[3]=t.w;
            t = *(const float4*)&Bs[kk][(tx << 3) + 4]; b[4]=t.x; b[5]=t.y; b[6]=t.z; b[7]=t.w;
#pragma unroll
            for (int i = 0; i < 8; i++)
#pragma unroll
                for (int j = 0; j < 8; j++)
                    acc[i][j] += a[i] * b[j];
        }
    }

    float bb[8];
#pragma unroll
    for (int j = 0; j < 8; j++) bb[j] = bias[bn + (tx << 3) + j];
#pragma unroll
    for (int i = 0; i < 8; i++) {
        const size_t row = bm + (ty << 3) + i;
        float4 r0 = make_float4(acc[i][0] + bb[0], acc[i][1] + bb[1],
                                acc[i][2] + bb[2], acc[i][3] + bb[3]);
        float4 r1 = make_float4(acc[i][4] + bb[4], acc[i][5] + bb[5],
                                acc[i][6] + bb[6], acc[i][7] + bb[7]);
        *(float4*)&C[row * N + bn + (tx << 3)] = r0;
        *(float4*)&C[row * N + bn + (tx << 3) + 4] = r1;
    }
}

// ---------------------------------------------------------------------------
// Fused RMSNorm + RoPE, in place. One block (256 thr) per token.
// ---------------------------------------------------------------------------
__global__ __launch_bounds__(256) void normrope_kernel(
    float* __restrict__ h, const float* __restrict__ g,
    const float* __restrict__ cs, const float* __restrict__ sn) {
    const int s = blockIdx.x;
    const int tid = threadIdx.x;

    float4 v = *(float4*)&h[(size_t)s * DIMV + (tid << 2)];
    float ss = v.x * v.x + v.y * v.y + v.z * v.z + v.w * v.w;
#pragma unroll
    for (int o = 16; o; o >>= 1) ss += __shfl_xor_sync(0xffffffffu, ss, o);

    __shared__ float red[8];
    __shared__ float rtot;
    if ((tid & 31) == 0) red[tid >> 5] = ss;
    __syncthreads();
    if (tid == 0) {
        float t = 0.f;
#pragma unroll
        for (int i = 0; i < 8; i++) t += red[i];
        rtot = rsqrtf(t * (1.0f / 1024.0f) + 1e-6f);
    }
    __syncthreads();
    const float r = rtot;

    float4 gv = *(const float4*)&g[tid << 2];
    const float a0 = v.x * r * gv.x, b0 = v.y * r * gv.y;
    const float a1 = v.z * r * gv.z, b1 = v.w * r * gv.w;

    const int p0 = tid << 1;                 // global pair indices p0, p0+1
    const int r0 = p0 & 31, r1 = (p0 + 1) & 31;
    const float c0 = cs[s * 32 + r0], s0 = sn[s * 32 + r0];
    const float c1 = cs[s * 32 + r1], s1 = sn[s * 32 + r1];

    float4 out;
    out.x = a0 * c0 - b0 * s0;
    out.y = a0 * s0 + b0 * c0;
    out.z = a1 * c1 - b1 * s1;
    out.w = a1 * s1 + b1 * c1;
    *(float4*)&h[(size_t)s * DIMV + (tid << 2)] = out;
}

// ---------------------------------------------------------------------------
// Windowed attention over dilated streams. Grid (136, 16, 2); 256 threads.
// 32 queries/block, one 8-lane group per query, Q held in registers.
// Online softmax; K/V tiles of 32 keys in smem.
// ---------------------------------------------------------------------------
__global__ __launch_bounds__(256) void attn_kernel(
    const float* __restrict__ qg, const float* __restrict__ kg,
    const float* __restrict__ vg, float* __restrict__ og) {
    const int d = blockIdx.z, h = blockIdx.y;
    const int q0 = blockIdx.x << 5;
    const int tid = threadIdx.x;
    const int qi = tid >> 3;
    const int l8 = tid & 7;
    const int pq = q0 + qi;              // always < SREAL (136*32 == 4352)

    __shared__ float Ks[32][68];
    __shared__ float Vs[32][68];
    __shared__ float Ps[32][36];

    float qr[8];
    {
        const int oq = dil2orig(d, pq);
        const float* qp = &qg[(size_t)oq * DIMV + h * HD + (l8 << 3)];
        const float4 x0 = *(const float4*)qp;
        const float4 x1 = *(const float4*)(qp + 4);
        const float sc = 0.125f;         // 1/sqrt(64)
        qr[0]=x0.x*sc; qr[1]=x0.y*sc; qr[2]=x0.z*sc; qr[3]=x0.w*sc;
        qr[4]=x1.x*sc; qr[5]=x1.y*sc; qr[6]=x1.z*sc; qr[7]=x1.w*sc;
    }

    float m = -3e38f, l = 0.f;
    float acc[8] = {0.f, 0.f, 0.f, 0.f, 0.f, 0.f, 0.f, 0.f};

    const int jlo = (q0 >= WIN) ? (q0 - WIN) : 0;
    const int jhi = min(SD - 1, q0 + 31 + WIN);

    for (int jt = jlo; jt <= jhi; jt += 32) {
        __syncthreads();
        {
            const int pk = jt + qi;
            float4 z = make_float4(0.f, 0.f, 0.f, 0.f);
            float4 k0 = z, k1 = z, v0 = z, v1 = z;
            if (pk <= jhi && pk < SREAL) {
                const int ok = dil2orig(d, pk);
                const float* kp = &kg[(size_t)ok * DIMV + h * HD + (l8 << 3)];
                const float* vp = &vg[(size_t)ok * DIMV + h * HD + (l8 << 3)];
                k0 = *(const float4*)kp; k1 = *(const float4*)(kp + 4);
                v0 = *(const float4*)vp; v1 = *(const float4*)(vp + 4);
            }
            *(float4*)&Ks[qi][l8 << 3] = k0;       *(float4*)&Ks[qi][(l8 << 3) + 4] = k1;
            *(float4*)&Vs[qi][l8 << 3] = v0;       *(float4*)&Vs[qi][(l8 << 3) + 4] = v1;
        }
        __syncthreads();

        // partial dot over this lane's 8 dims for all 32 keys
        float part[32];
#pragma unroll
        for (int kk = 0; kk < 32; kk++) {
            const float4 ka = *(const float4*)&Ks[kk][l8 << 3];
            const float4 kb = *(const float4*)&Ks[kk][(l8 << 3) + 4];
            part[kk] = qr[0]*ka.x + qr[1]*ka.y + qr[2]*ka.z + qr[3]*ka.w
                     + qr[4]*kb.x + qr[5]*kb.y + qr[6]*kb.z + qr[7]*kb.w;
        }
        // butterfly all-reduce over the 8-lane group → full dot products
#pragma unroll
        for (int off = 1; off < 8; off <<= 1)
#pragma unroll
            for (int kk = 0; kk < 32; kk++)
                part[kk] += __shfl_xor_sync(0xffffffffu, part[kk], off, 8);

        float scv[4];
        float tm = -3e38f;
#pragma unroll
        for (int t = 0; t < 4; t++) {
            const int kk = l8 + (t << 3);
            const int pk = jt + kk;
            const bool valid = (pk <= jhi) && (pk - pq <= WIN) && (pq - pk <= WIN);
            scv[t] = valid ? part[kk] : -1e9f;
            tm = fmaxf(tm, scv[t]);
        }
#pragma unroll
        for (int off = 4; off; off >>= 1)
            tm = fmaxf(tm, __shfl_xor_sync(0xffffffffu, tm, off, 8));

        const float mnew = fmaxf(m, tm);
        const float corr = __expf(m - mnew);
        l *= corr;
#pragma unroll
        for (int i = 0; i < 8; i++) acc[i] *= corr;

        float ls = 0.f;
#pragma unroll
        for (int t = 0; t < 4; t++) {
            const float p = __expf(scv[t] - mnew);
            ls += p;
            Ps[qi][l8 + (t << 3)] = p;
        }
#pragma unroll
        for (int off = 4; off; off >>= 1)
            ls += __shfl_xor_sync(0xffffffffu, ls, off, 8);
        l += ls;
        m = mnew;
        __syncwarp();

#pragma unroll
        for (int kk = 0; kk < 32; kk++) {
            const float pv = Ps[qi][kk];
            const float4 va = *(const float4*)&Vs[kk][l8 << 3];
            const float4 vb = *(const float4*)&Vs[kk][(l8 << 3) + 4];
            acc[0] += pv * va.x; acc[1] += pv * va.y;
            acc[2] += pv * va.z; acc[3] += pv * va.w;
            acc[4] += pv * vb.x; acc[5] += pv * vb.y;
            acc[6] += pv * vb.z; acc[7] += pv * vb.w;
        }
    }

    const float inv = 1.0f / l;
    const int oq = dil2orig(d, pq);
    float4 r0 = make_float4(acc[0]*inv, acc[1]*inv, acc[2]*inv, acc[3]*inv);
    float4 r1 = make_float4(acc[4]*inv, acc[5]*inv, acc[6]*inv, acc[7]*inv);
    float* op = &og[(size_t)oq * DIMV + h * HD + (l8 << 3)];
    *(float4*)op = r0;
    *(float4*)(op + 4) = r1;
}

// ---------------------------------------------------------------------------
extern "C" void kernel_launch(void* const* d_in, const int* in_sizes, int n_in,
                              void* d_out, int out_size) {
    (void)in_sizes; (void)n_in; (void)out_size;
    const float* x  = (const float*)d_in[0];
    const float* fc = (const float*)d_in[1];
    const float* fs = (const float*)d_in[2];
    const float* wq = (const float*)d_in[3];
    const float* bq = (const float*)d_in[4];
    const float* wk = (const float*)d_in[5];
    const float* bk = (const float*)d_in[6];
    const float* wv = (const float*)d_in[7];
    const float* bv = (const float*)d_in[8];
    const float* wo = (const float*)d_in[9];
    const float* bo = (const float*)d_in[10];
    const float* gq = (const float*)d_in[11];
    const float* gk = (const float*)d_in[12];
    float* out = (float*)d_out;

    float *qb, *kb, *vb, *ob;
    cudaGetSymbolAddress((void**)&qb, g_q);
    cudaGetSymbolAddress((void**)&kb, g_k);
    cudaGetSymbolAddress((void**)&vb, g_v);
    cudaGetSymbolAddress((void**)&ob, g_o);

    const dim3 ggrid(DIMV / 128, S_LEN / 128);
    gemm_bias_kernel<<<ggrid, 256>>>(x, wq, bq, qb, S_LEN, DIMV, DIMV);
    gemm_bias_kernel<<<ggrid, 256>>>(x, wk, bk, kb, S_LEN, DIMV, DIMV);
    gemm_bias_kernel<<<ggrid, 256>>>(x, wv, bv, vb, S_LEN, DIMV, DIMV);

    normrope_kernel<<<S_LEN, 256>>>(qb, gq, fc, fs);
    normrope_kernel<<<S_LEN, 256>>>(kb, gk, fc, fs);

    attn_kernel<<<dim3(SREAL / 32, NH, 2), 256>>>(qb, kb, vb, ob);

    gemm_bias_kernel<<<ggrid, 256>>>(ob, wo, bo, out, S_LEN, DIMV, DIMV);
}

// round 4
// speedup vs baseline: 1.1664x; 1.1664x over previous
#include <cuda_runtime.h>
#include <cuda_bf16.h>
#include <math.h>
#include <stdint.h>

#define S_LEN 8704
#define DIMV  1024
#define NH    16
#define HD    64
#define SD    4608   // dilated stream length (incl. zero padding block)
#define SREAL 4352   // real tokens per stream
#define WIN   512

// fp32 activation buffers
__device__ float g_q[S_LEN * DIMV];
__device__ float g_k[S_LEN * DIMV];
__device__ float g_v[S_LEN * DIMV];
__device__ float g_o[S_LEN * DIMV];

// bf16 split activations (reused for x and attention output)
__device__ __nv_bfloat16 g_ahi[S_LEN * DIMV];
__device__ __nv_bfloat16 g_alo[S_LEN * DIMV];

// bf16 split transposed weights [N][K]
__device__ __nv_bfloat16 g_wqT_hi[DIMV * DIMV];
__device__ __nv_bfloat16 g_wqT_lo[DIMV * DIMV];
__device__ __nv_bfloat16 g_wkT_hi[DIMV * DIMV];
__device__ __nv_bfloat16 g_wkT_lo[DIMV * DIMV];
__device__ __nv_bfloat16 g_wvT_hi[DIMV * DIMV];
__device__ __nv_bfloat16 g_wvT_lo[DIMV * DIMV];
__device__ __nv_bfloat16 g_woT_hi[DIMV * DIMV];
__device__ __nv_bfloat16 g_woT_lo[DIMV * DIMV];

__device__ __forceinline__ int dil2orig(int d, int p) {
    return ((p >> 8) << 9) + (d << 8) + (p & 255);
}

__device__ __forceinline__ uint32_t smem_to_u32(const void* smem_ptr) {
    uint32_t addr;
    asm("{ .reg .u64 tmp; cvta.to.shared.u64 tmp, %1; cvt.u32.u64 %0, tmp; }"
        : "=r"(addr) : "l"(smem_ptr));
    return addr;
}

// ===========================================================================
// family-generic tensor-core primitives (sm_80-era PTX, valid on sm_103 base)
// ===========================================================================
__device__ __forceinline__ void ldsm4(uint32_t* r, uint32_t addr) {
    asm volatile("ldmatrix.sync.aligned.m8n8.x4.shared.b16 {%0,%1,%2,%3}, [%4];\n"
                 : "=r"(r[0]), "=r"(r[1]), "=r"(r[2]), "=r"(r[3]) : "r"(addr));
}
__device__ __forceinline__ void mma16816(float* c, const uint32_t* a,
                                         uint32_t b0, uint32_t b1) {
    asm volatile(
        "mma.sync.aligned.m16n8k16.row.col.f32.bf16.bf16.f32 "
        "{%0,%1,%2,%3}, {%4,%5,%6,%7}, {%8,%9}, {%0,%1,%2,%3};\n"
        : "+f"(c[0]), "+f"(c[1]), "+f"(c[2]), "+f"(c[3])
        : "r"(a[0]), "r"(a[1]), "r"(a[2]), "r"(a[3]), "r"(b0), "r"(b1));
}
__device__ __forceinline__ void cp_async16(uint32_t saddr, const void* gptr) {
    asm volatile("cp.async.cg.shared.global [%0], [%1], 16;\n"
                 :: "r"(saddr), "l"(gptr));
}
#define CP_COMMIT() asm volatile("cp.async.commit_group;\n" ::: "memory")
#define CP_WAIT0()  asm volatile("cp.async.wait_group 0;\n" ::: "memory")

// smem tile layout: 128 rows x 32 bf16 (4 x 16B chunks/row), swizzled so
// ldmatrix (8 rows x same chunk) hits 8 distinct bank-quads.
__device__ __forceinline__ uint32_t sw_off(int r, int c) {
    return (uint32_t)(((r >> 1) << 7) + ((r & 1) << 6) +
                      (((c ^ ((r >> 1) & 3)) & 3) << 4));
}

// ===========================================================================
// bf16 split helpers
// ===========================================================================
__device__ __forceinline__ void bsplit(float f, __nv_bfloat16& h, __nv_bfloat16& l) {
    h = __float2bfloat16(f);
    l = __float2bfloat16(f - __bfloat162float(h));
}

struct __align__(8) B4 { __nv_bfloat16 v[4]; };

// elementwise split: fp32 [n] -> bf16 hi/lo, 4 elems/thread
__global__ __launch_bounds__(256) void split_kernel(
    const float* __restrict__ src, __nv_bfloat16* __restrict__ hi,
    __nv_bfloat16* __restrict__ lo) {
    const int idx = blockIdx.x * 256 + threadIdx.x;
    float4 v = ((const float4*)src)[idx];
    B4 h, l;
    bsplit(v.x, h.v[0], l.v[0]);
    bsplit(v.y, h.v[1], l.v[1]);
    bsplit(v.z, h.v[2], l.v[2]);
    bsplit(v.w, h.v[3], l.v[3]);
    ((B4*)hi)[idx] = h;
    ((B4*)lo)[idx] = l;
}

// transpose + split: w[K][N] fp32 -> hiT/loT [N][K] bf16
__global__ __launch_bounds__(256) void wsplit_kernel(
    const float* __restrict__ w, __nv_bfloat16* __restrict__ hiT,
    __nv_bfloat16* __restrict__ loT) {
    __shared__ float t[32][33];
    const int bx = blockIdx.x << 5;   // n base
    const int by = blockIdx.y << 5;   // k base
    const int tx = threadIdx.x, ty = threadIdx.y;   // 32 x 8
#pragma unroll
    for (int i = 0; i < 32; i += 8)
        t[ty + i][tx] = w[(size_t)(by + ty + i) * DIMV + bx + tx];
    __syncthreads();
#pragma unroll
    for (int i = 0; i < 32; i += 8) {
        const float f = t[tx][ty + i];   // w[by+tx][bx+ty+i]
        __nv_bfloat16 h, l;
        bsplit(f, h, l);
        const size_t o = (size_t)(bx + ty + i) * DIMV + by + tx;
        hiT[o] = h;
        loT[o] = l;
    }
}

// ===========================================================================
// HMMA split-precision GEMM:
// C[M,1024] = Ahi@BhiT + Ahi@BloT + Alo@BhiT + bias, fp32 mma.sync accum.
// CTA tile 128x128, K-stage 32, 8 warps x (64x32) warp tiles, cp.async 2-stage.
// grid (N/128, M/128), 256 threads.
// ===========================================================================
#define STAGE_BYTES 32768       // 4 tiles x 8KB (Ahi, Alo, Bhi, Blo)
#define GEMM_SMEM_REQ (2 * STAGE_BYTES)

__device__ __forceinline__ void load_stage(
    uint32_t sbase, const __nv_bfloat16* __restrict__ Ahi,
    const __nv_bfloat16* __restrict__ Alo,
    const __nv_bfloat16* __restrict__ Bhi,
    const __nv_bfloat16* __restrict__ Blo,
    int bm, int bn, int k0, int tid) {
#pragma unroll
    for (int j = 0; j < 8; j++) {
        const int chunk = tid + (j << 8);
        const int tile = chunk >> 9;          // 0..3
        const int idx = chunk & 511;
        const int r = idx >> 2, c = idx & 3;
        const uint32_t saddr = sbase + (uint32_t)(tile << 13) + sw_off(r, c);
        const __nv_bfloat16* gp;
        if (tile == 0)      gp = Ahi + (size_t)(bm + r) * DIMV + k0 + c * 8;
        else if (tile == 1) gp = Alo + (size_t)(bm + r) * DIMV + k0 + c * 8;
        else if (tile == 2) gp = Bhi + (size_t)(bn + r) * DIMV + k0 + c * 8;
        else                gp = Blo + (size_t)(bn + r) * DIMV + k0 + c * 8;
        cp_async16(saddr, gp);
    }
}

__global__ __launch_bounds__(256, 2)
void gemm_mma_kernel(const __nv_bfloat16* __restrict__ Ahi,
                     const __nv_bfloat16* __restrict__ Alo,
                     const __nv_bfloat16* __restrict__ Bhi,
                     const __nv_bfloat16* __restrict__ Blo,
                     const float* __restrict__ bias,
                     float* __restrict__ C) {
    extern __shared__ char smem[];
    const uint32_t sb = smem_to_u32(smem);
    const int tid = threadIdx.x;
    const int bn = blockIdx.x << 7;
    const int bm = blockIdx.y << 7;
    const int wid = tid >> 5, lane = tid & 31;
    const int wm = (wid & 1) << 6;     // warp m offset (0 | 64)
    const int wn = (wid >> 1) << 5;    // warp n offset (0..96)
    const int lr = lane & 15;          // ldmatrix row within 16
    const int lhalf = lane >> 4;       // ldmatrix k-chunk half

    float acc[4][4][4];
#pragma unroll
    for (int i = 0; i < 4; i++)
#pragma unroll
        for (int j = 0; j < 4; j++)
#pragma unroll
            for (int k = 0; k < 4; k++) acc[i][j][k] = 0.f;

    load_stage(sb, Ahi, Alo, Bhi, Blo, bm, bn, 0, tid);
    CP_COMMIT();

    for (int s = 0; s < 32; s++) {
        CP_WAIT0();
        __syncthreads();
        if (s + 1 < 32) {
            load_stage(sb + ((s + 1) & 1) * STAGE_BYTES, Ahi, Alo, Bhi, Blo,
                       bm, bn, (s + 1) << 5, tid);
            CP_COMMIT();
        }

        const uint32_t buf = sb + (s & 1) * STAGE_BYTES;
#pragma unroll
        for (int kk = 0; kk < 2; kk++) {
            const int cb = (kk << 1) + lhalf;
            uint32_t a[4][4], b[2][4];
            // pass 1: Ahi x Bhi
#pragma unroll
            for (int mi = 0; mi < 4; mi++)
                ldsm4(a[mi], buf + sw_off(wm + (mi << 4) + lr, cb));
#pragma unroll
            for (int np = 0; np < 2; np++)
                ldsm4(b[np], buf + 16384 + sw_off(wn + (np << 4) + lr, cb));
#pragma unroll
            for (int mi = 0; mi < 4; mi++) {
                mma16816(acc[mi][0], a[mi], b[0][0], b[0][2]);
                mma16816(acc[mi][1], a[mi], b[0][1], b[0][3]);
                mma16816(acc[mi][2], a[mi], b[1][0], b[1][2]);
                mma16816(acc[mi][3], a[mi], b[1][1], b[1][3]);
            }
            // pass 2: Ahi x Blo
#pragma unroll
            for (int np = 0; np < 2; np++)
                ldsm4(b[np], buf + 24576 + sw_off(wn + (np << 4) + lr, cb));
#pragma unroll
            for (int mi = 0; mi < 4; mi++) {
                mma16816(acc[mi][0], a[mi], b[0][0], b[0][2]);
                mma16816(acc[mi][1], a[mi], b[0][1], b[0][3]);
                mma16816(acc[mi][2], a[mi], b[1][0], b[1][2]);
                mma16816(acc[mi][3], a[mi], b[1][1], b[1][3]);
            }
            // pass 3: Alo x Bhi
#pragma unroll
            for (int mi = 0; mi < 4; mi++)
                ldsm4(a[mi], buf + 8192 + sw_off(wm + (mi << 4) + lr, cb));
#pragma unroll
            for (int np = 0; np < 2; np++)
                ldsm4(b[np], buf + 16384 + sw_off(wn + (np << 4) + lr, cb));
#pragma unroll
            for (int mi = 0; mi < 4; mi++) {
                mma16816(acc[mi][0], a[mi], b[0][0], b[0][2]);
                mma16816(acc[mi][1], a[mi], b[0][1], b[0][3]);
                mma16816(acc[mi][2], a[mi], b[1][0], b[1][2]);
                mma16816(acc[mi][3], a[mi], b[1][1], b[1][3]);
            }
        }
        __syncthreads();
    }

    // epilogue: add bias, store fp32
    const int crow = lane >> 2;
    const int ccol = (lane & 3) << 1;
#pragma unroll
    for (int ni = 0; ni < 4; ni++) {
        const int col = bn + wn + (ni << 3) + ccol;
        const float2 bv = *(const float2*)&bias[col];
#pragma unroll
        for (int mi = 0; mi < 4; mi++) {
            const int row = bm + wm + (mi << 4) + crow;
            float2 o0 = make_float2(acc[mi][ni][0] + bv.x, acc[mi][ni][1] + bv.y);
            float2 o1 = make_float2(acc[mi][ni][2] + bv.x, acc[mi][ni][3] + bv.y);
            *(float2*)&C[(size_t)row * DIMV + col] = o0;
            *(float2*)&C[(size_t)(row + 8) * DIMV + col] = o1;
        }
    }
}

// ---------------------------------------------------------------------------
// Fused RMSNorm + RoPE, in place. One block (256 thr) per token.
// ---------------------------------------------------------------------------
__global__ __launch_bounds__(256) void normrope_kernel(
    float* __restrict__ h, const float* __restrict__ g,
    const float* __restrict__ cs, const float* __restrict__ sn) {
    const int s = blockIdx.x;
    const int tid = threadIdx.x;

    float4 v = *(float4*)&h[(size_t)s * DIMV + (tid << 2)];
    float ss = v.x * v.x + v.y * v.y + v.z * v.z + v.w * v.w;
#pragma unroll
    for (int o = 16; o; o >>= 1) ss += __shfl_xor_sync(0xffffffffu, ss, o);

    __shared__ float red[8];
    __shared__ float rtot;
    if ((tid & 31) == 0) red[tid >> 5] = ss;
    __syncthreads();
    if (tid == 0) {
        float t = 0.f;
#pragma unroll
        for (int i = 0; i < 8; i++) t += red[i];
        rtot = rsqrtf(t * (1.0f / 1024.0f) + 1e-6f);
    }
    __syncthreads();
    const float r = rtot;

    float4 gv = *(const float4*)&g[tid << 2];
    const float a0 = v.x * r * gv.x, b0 = v.y * r * gv.y;
    const float a1 = v.z * r * gv.z, b1 = v.w * r * gv.w;

    const int p0 = tid << 1;
    const int r0 = p0 & 31, r1 = (p0 + 1) & 31;
    const float c0 = cs[s * 32 + r0], s0 = sn[s * 32 + r0];
    const float c1 = cs[s * 32 + r1], s1 = sn[s * 32 + r1];

    float4 out;
    out.x = a0 * c0 - b0 * s0;
    out.y = a0 * s0 + b0 * c0;
    out.z = a1 * c1 - b1 * s1;
    out.w = a1 * s1 + b1 * c1;
    *(float4*)&h[(size_t)s * DIMV + (tid << 2)] = out;
}

// ---------------------------------------------------------------------------
// Windowed attention over dilated streams. Grid (136, 16, 2); 256 threads.
// ---------------------------------------------------------------------------
__global__ __launch_bounds__(256) void attn_kernel(
    const float* __restrict__ qg, const float* __restrict__ kg,
    const float* __restrict__ vg, float* __restrict__ og) {
    const int d = blockIdx.z, h = blockIdx.y;
    const int q0 = blockIdx.x << 5;
    const int tid = threadIdx.x;
    const int qi = tid >> 3;
    const int l8 = tid & 7;
    const int pq = q0 + qi;

    __shared__ float Ks[32][68];
    __shared__ float Vs[32][68];
    __shared__ float Ps[32][36];

    float qr[8];
    {
        const int oq = dil2orig(d, pq);
        const float* qp = &qg[(size_t)oq * DIMV + h * HD + (l8 << 3)];
        const float4 x0 = *(const float4*)qp;
        const float4 x1 = *(const float4*)(qp + 4);
        const float sc = 0.125f;
        qr[0]=x0.x*sc; qr[1]=x0.y*sc; qr[2]=x0.z*sc; qr[3]=x0.w*sc;
        qr[4]=x1.x*sc; qr[5]=x1.y*sc; qr[6]=x1.z*sc; qr[7]=x1.w*sc;
    }

    float m = -3e38f, l = 0.f;
    float acc[8] = {0.f, 0.f, 0.f, 0.f, 0.f, 0.f, 0.f, 0.f};

    const int jlo = (q0 >= WIN) ? (q0 - WIN) : 0;
    const int jhi = min(SD - 1, q0 + 31 + WIN);

    for (int jt = jlo; jt <= jhi; jt += 32) {
        __syncthreads();
        {
            const int pk = jt + qi;
            float4 z = make_float4(0.f, 0.f, 0.f, 0.f);
            float4 k0 = z, k1 = z, v0 = z, v1 = z;
            if (pk <= jhi && pk < SREAL) {
                const int ok = dil2orig(d, pk);
                const float* kp = &kg[(size_t)ok * DIMV + h * HD + (l8 << 3)];
                const float* vp = &vg[(size_t)ok * DIMV + h * HD + (l8 << 3)];
                k0 = *(const float4*)kp; k1 = *(const float4*)(kp + 4);
                v0 = *(const float4*)vp; v1 = *(const float4*)(vp + 4);
            }
            *(float4*)&Ks[qi][l8 << 3] = k0;       *(float4*)&Ks[qi][(l8 << 3) + 4] = k1;
            *(float4*)&Vs[qi][l8 << 3] = v0;       *(float4*)&Vs[qi][(l8 << 3) + 4] = v1;
        }
        __syncthreads();

        float part[32];
#pragma unroll
        for (int kk = 0; kk < 32; kk++) {
            const float4 ka = *(const float4*)&Ks[kk][l8 << 3];
            const float4 kb = *(const float4*)&Ks[kk][(l8 << 3) + 4];
            part[kk] = qr[0]*ka.x + qr[1]*ka.y + qr[2]*ka.z + qr[3]*ka.w
                     + qr[4]*kb.x + qr[5]*kb.y + qr[6]*kb.z + qr[7]*kb.w;
        }
#pragma unroll
        for (int off = 1; off < 8; off <<= 1)
#pragma unroll
            for (int kk = 0; kk < 32; kk++)
                part[kk] += __shfl_xor_sync(0xffffffffu, part[kk], off, 8);

        float scv[4];
        float tm = -3e38f;
#pragma unroll
        for (int t = 0; t < 4; t++) {
            const int kk = l8 + (t << 3);
            const int pk = jt + kk;
            const bool valid = (pk <= jhi) && (pk - pq <= WIN) && (pq - pk <= WIN);
            scv[t] = valid ? part[kk] : -1e9f;
            tm = fmaxf(tm, scv[t]);
        }
#pragma unroll
        for (int off = 4; off; off >>= 1)
            tm = fmaxf(tm, __shfl_xor_sync(0xffffffffu, tm, off, 8));

        const float mnew = fmaxf(m, tm);
        const float corr = __expf(m - mnew);
        l *= corr;
#pragma unroll
        for (int i = 0; i < 8; i++) acc[i] *= corr;

        float ls = 0.f;
#pragma unroll
        for (int t = 0; t < 4; t++) {
            const float p = __expf(scv[t] - mnew);
            ls += p;
            Ps[qi][l8 + (t << 3)] = p;
        }
#pragma unroll
        for (int off = 4; off; off >>= 1)
            ls += __shfl_xor_sync(0xffffffffu, ls, off, 8);
        l += ls;
        m = mnew;
        __syncwarp();

#pragma unroll
        for (int kk = 0; kk < 32; kk++) {
            const float pv = Ps[qi][kk];
            const float4 va = *(const float4*)&Vs[kk][l8 << 3];
            const float4 vb = *(const float4*)&Vs[kk][(l8 << 3) + 4];
            acc[0] += pv * va.x; acc[1] += pv * va.y;
            acc[2] += pv * va.z; acc[3] += pv * va.w;
            acc[4] += pv * vb.x; acc[5] += pv * vb.y;
            acc[6] += pv * vb.z; acc[7] += pv * vb.w;
        }
    }

    const float inv = 1.0f / l;
    const int oq = dil2orig(d, pq);
    float4 r0 = make_float4(acc[0]*inv, acc[1]*inv, acc[2]*inv, acc[3]*inv);
    float4 r1 = make_float4(acc[4]*inv, acc[5]*inv, acc[6]*inv, acc[7]*inv);
    float* op = &og[(size_t)oq * DIMV + h * HD + (l8 << 3)];
    *(float4*)op = r0;
    *(float4*)(op + 4) = r1;
}

// ---------------------------------------------------------------------------
extern "C" void kernel_launch(void* const* d_in, const int* in_sizes, int n_in,
                              void* d_out, int out_size) {
    (void)in_sizes; (void)n_in; (void)out_size;
    const float* x  = (const float*)d_in[0];
    const float* fc = (const float*)d_in[1];
    const float* fs = (const float*)d_in[2];
    const float* wq = (const float*)d_in[3];
    const float* bq = (const float*)d_in[4];
    const float* wk = (const float*)d_in[5];
    const float* bk = (const float*)d_in[6];
    const float* wv = (const float*)d_in[7];
    const float* bv = (const float*)d_in[8];
    const float* wo = (const float*)d_in[9];
    const float* bo = (const float*)d_in[10];
    const float* gq = (const float*)d_in[11];
    const float* gk = (const float*)d_in[12];
    float* out = (float*)d_out;

    float *qb, *kb, *vb, *ob;
    cudaGetSymbolAddress((void**)&qb, g_q);
    cudaGetSymbolAddress((void**)&kb, g_k);
    cudaGetSymbolAddress((void**)&vb, g_v);
    cudaGetSymbolAddress((void**)&ob, g_o);
    __nv_bfloat16 *ahi, *alo;
    cudaGetSymbolAddress((void**)&ahi, g_ahi);
    cudaGetSymbolAddress((void**)&alo, g_alo);
    __nv_bfloat16 *wqh, *wql, *wkh, *wkl, *wvh, *wvl, *woh, *wol;
    cudaGetSymbolAddress((void**)&wqh, g_wqT_hi);
    cudaGetSymbolAddress((void**)&wql, g_wqT_lo);
    cudaGetSymbolAddress((void**)&wkh, g_wkT_hi);
    cudaGetSymbolAddress((void**)&wkl, g_wkT_lo);
    cudaGetSymbolAddress((void**)&wvh, g_wvT_hi);
    cudaGetSymbolAddress((void**)&wvl, g_wvT_lo);
    cudaGetSymbolAddress((void**)&woh, g_woT_hi);
    cudaGetSymbolAddress((void**)&wol, g_woT_lo);

    cudaFuncSetAttribute(gemm_mma_kernel,
                         cudaFuncAttributeMaxDynamicSharedMemorySize, GEMM_SMEM_REQ);

    const dim3 wgrid(32, 32);
    const dim3 wblk(32, 8);
    wsplit_kernel<<<wgrid, wblk>>>(wq, wqh, wql);
    wsplit_kernel<<<wgrid, wblk>>>(wk, wkh, wkl);
    wsplit_kernel<<<wgrid, wblk>>>(wv, wvh, wvl);
    wsplit_kernel<<<wgrid, wblk>>>(wo, woh, wol);

    split_kernel<<<(S_LEN * DIMV) / 1024, 256>>>(x, ahi, alo);

    const dim3 ggrid(DIMV / 128, S_LEN / 128);
    gemm_mma_kernel<<<ggrid, 256, GEMM_SMEM_REQ>>>(ahi, alo, wqh, wql, bq, qb);
    gemm_mma_kernel<<<ggrid, 256, GEMM_SMEM_REQ>>>(ahi, alo, wkh, wkl, bk, kb);
    gemm_mma_kernel<<<ggrid, 256, GEMM_SMEM_REQ>>>(ahi, alo, wvh, wvl, bv, vb);

    normrope_kernel<<<S_LEN, 256>>>(qb, gq, fc, fs);
    normrope_kernel<<<S_LEN, 256>>>(kb, gk, fc, fs);

    attn_kernel<<<dim3(SREAL / 32, NH, 2), 256>>>(qb, kb, vb, ob);

    split_kernel<<<(S_LEN * DIMV) / 1024, 256>>>(ob, ahi, alo);
    gemm_mma_kernel<<<ggrid, 256, GEMM_SMEM_REQ>>>(ahi, alo, woh, wol, bo, out);
}

// round 5
// speedup vs baseline: 5.6987x; 4.8856x over previous
#include <cuda_runtime.h>
#include <cuda_bf16.h>
#include <math.h>
#include <stdint.h>

#define S_LEN 8704
#define DIMV  1024
#define NH    16
#define HD    64
#define SD    4608   // dilated stream length (incl. zero padding block)
#define SREAL 4352   // real tokens per stream
#define WIN   512
#define BQ    64
#define BK    64

// fp32 activation buffers
__device__ float g_q[S_LEN * DIMV];
__device__ float g_k[S_LEN * DIMV];
__device__ float g_v[S_LEN * DIMV];

// bf16 split activations
__device__ __nv_bfloat16 g_ahi[S_LEN * DIMV];
__device__ __nv_bfloat16 g_alo[S_LEN * DIMV];
__device__ __nv_bfloat16 g_qhi[S_LEN * DIMV];
__device__ __nv_bfloat16 g_qlo[S_LEN * DIMV];
__device__ __nv_bfloat16 g_khi[S_LEN * DIMV];
__device__ __nv_bfloat16 g_klo[S_LEN * DIMV];
__device__ __nv_bfloat16 g_vhi[S_LEN * DIMV];
__device__ __nv_bfloat16 g_vlo[S_LEN * DIMV];

// bf16 split transposed weights [N][K]
__device__ __nv_bfloat16 g_wqT_hi[DIMV * DIMV];
__device__ __nv_bfloat16 g_wqT_lo[DIMV * DIMV];
__device__ __nv_bfloat16 g_wkT_hi[DIMV * DIMV];
__device__ __nv_bfloat16 g_wkT_lo[DIMV * DIMV];
__device__ __nv_bfloat16 g_wvT_hi[DIMV * DIMV];
__device__ __nv_bfloat16 g_wvT_lo[DIMV * DIMV];
__device__ __nv_bfloat16 g_woT_hi[DIMV * DIMV];
__device__ __nv_bfloat16 g_woT_lo[DIMV * DIMV];

__device__ __forceinline__ int dil2orig(int d, int p) {
    return ((p >> 8) << 9) + (d << 8) + (p & 255);
}

__device__ __forceinline__ uint32_t smem_to_u32(const void* smem_ptr) {
    uint32_t addr;
    asm("{ .reg .u64 tmp; cvta.to.shared.u64 tmp, %1; cvt.u32.u64 %0, tmp; }"
        : "=r"(addr) : "l"(smem_ptr));
    return addr;
}

// ===========================================================================
// family-generic tensor-core primitives (sm_80-era PTX, valid on sm_103 base)
// ===========================================================================
__device__ __forceinline__ void ldsm4(uint32_t* r, uint32_t addr) {
    asm volatile("ldmatrix.sync.aligned.m8n8.x4.shared.b16 {%0,%1,%2,%3}, [%4];\n"
                 : "=r"(r[0]), "=r"(r[1]), "=r"(r[2]), "=r"(r[3]) : "r"(addr));
}
__device__ __forceinline__ void ldsm4t(uint32_t* r, uint32_t addr) {
    asm volatile("ldmatrix.sync.aligned.m8n8.x4.trans.shared.b16 {%0,%1,%2,%3}, [%4];\n"
                 : "=r"(r[0]), "=r"(r[1]), "=r"(r[2]), "=r"(r[3]) : "r"(addr));
}
__device__ __forceinline__ void mma16816(float* c, const uint32_t* a,
                                         uint32_t b0, uint32_t b1) {
    asm volatile(
        "mma.sync.aligned.m16n8k16.row.col.f32.bf16.bf16.f32 "
        "{%0,%1,%2,%3}, {%4,%5,%6,%7}, {%8,%9}, {%0,%1,%2,%3};\n"
        : "+f"(c[0]), "+f"(c[1]), "+f"(c[2]), "+f"(c[3])
        : "r"(a[0]), "r"(a[1]), "r"(a[2]), "r"(a[3]), "r"(b0), "r"(b1));
}
__device__ __forceinline__ void cp_async16(uint32_t saddr, const void* gptr) {
    asm volatile("cp.async.cg.shared.global [%0], [%1], 16;\n"
                 :: "r"(saddr), "l"(gptr));
}
__device__ __forceinline__ void cp_async16z(uint32_t saddr, const void* gptr, int srcbytes) {
    asm volatile("cp.async.cg.shared.global [%0], [%1], 16, %2;\n"
                 :: "r"(saddr), "l"(gptr), "r"(srcbytes));
}
#define CP_COMMIT() asm volatile("cp.async.commit_group;\n" ::: "memory")
#define CP_WAIT0()  asm volatile("cp.async.wait_group 0;\n" ::: "memory")

// gemm smem tile layout: 128 rows x 32 bf16 (4 x 16B chunks/row)
__device__ __forceinline__ uint32_t sw_off(int r, int c) {
    return (uint32_t)(((r >> 1) << 7) + ((r & 1) << 6) +
                      (((c ^ ((r >> 1) & 3)) & 3) << 4));
}
// attn smem tile layout: 64 rows x 64 bf16 (8 x 16B chunks/row), xor swizzle
__device__ __forceinline__ uint32_t att_off(int r, int ch) {
    return (uint32_t)((r << 7) + (((ch ^ (r & 7)) & 7) << 4));
}

__device__ __forceinline__ uint32_t pack_bf16x2(float a, float b) {
    __nv_bfloat162 t = __floats2bfloat162_rn(a, b);   // x=a(lo), y=b(hi)
    return *(uint32_t*)&t;
}

// ===========================================================================
// bf16 split helpers
// ===========================================================================
__device__ __forceinline__ void bsplit(float f, __nv_bfloat16& h, __nv_bfloat16& l) {
    h = __float2bfloat16(f);
    l = __float2bfloat16(f - __bfloat162float(h));
}

struct __align__(8) B4 { __nv_bfloat16 v[4]; };

__global__ __launch_bounds__(256) void split_kernel(
    const float* __restrict__ src, __nv_bfloat16* __restrict__ hi,
    __nv_bfloat16* __restrict__ lo) {
    const int idx = blockIdx.x * 256 + threadIdx.x;
    float4 v = ((const float4*)src)[idx];
    B4 h, l;
    bsplit(v.x, h.v[0], l.v[0]);
    bsplit(v.y, h.v[1], l.v[1]);
    bsplit(v.z, h.v[2], l.v[2]);
    bsplit(v.w, h.v[3], l.v[3]);
    ((B4*)hi)[idx] = h;
    ((B4*)lo)[idx] = l;
}

// transpose + split: w[K][N] fp32 -> hiT/loT [N][K] bf16
__global__ __launch_bounds__(256) void wsplit_kernel(
    const float* __restrict__ w, __nv_bfloat16* __restrict__ hiT,
    __nv_bfloat16* __restrict__ loT) {
    __shared__ float t[32][33];
    const int bx = blockIdx.x << 5;
    const int by = blockIdx.y << 5;
    const int tx = threadIdx.x, ty = threadIdx.y;
#pragma unroll
    for (int i = 0; i < 32; i += 8)
        t[ty + i][tx] = w[(size_t)(by + ty + i) * DIMV + bx + tx];
    __syncthreads();
#pragma unroll
    for (int i = 0; i < 32; i += 8) {
        const float f = t[tx][ty + i];
        __nv_bfloat16 h, l;
        bsplit(f, h, l);
        const size_t o = (size_t)(bx + ty + i) * DIMV + by + tx;
        hiT[o] = h;
        loT[o] = l;
    }
}

// ===========================================================================
// HMMA split-precision GEMM (same as R4, verified)
// ===========================================================================
#define STAGE_BYTES 32768
#define GEMM_SMEM_REQ (2 * STAGE_BYTES)

__device__ __forceinline__ void load_stage(
    uint32_t sbase, const __nv_bfloat16* __restrict__ Ahi,
    const __nv_bfloat16* __restrict__ Alo,
    const __nv_bfloat16* __restrict__ Bhi,
    const __nv_bfloat16* __restrict__ Blo,
    int bm, int bn, int k0, int tid) {
#pragma unroll
    for (int j = 0; j < 8; j++) {
        const int chunk = tid + (j << 8);
        const int tile = chunk >> 9;
        const int idx = chunk & 511;
        const int r = idx >> 2, c = idx & 3;
        const uint32_t saddr = sbase + (uint32_t)(tile << 13) + sw_off(r, c);
        const __nv_bfloat16* gp;
        if (tile == 0)      gp = Ahi + (size_t)(bm + r) * DIMV + k0 + c * 8;
        else if (tile == 1) gp = Alo + (size_t)(bm + r) * DIMV + k0 + c * 8;
        else if (tile == 2) gp = Bhi + (size_t)(bn + r) * DIMV + k0 + c * 8;
        else                gp = Blo + (size_t)(bn + r) * DIMV + k0 + c * 8;
        cp_async16(saddr, gp);
    }
}

__global__ __launch_bounds__(256, 2)
void gemm_mma_kernel(const __nv_bfloat16* __restrict__ Ahi,
                     const __nv_bfloat16* __restrict__ Alo,
                     const __nv_bfloat16* __restrict__ Bhi,
                     const __nv_bfloat16* __restrict__ Blo,
                     const float* __restrict__ bias,
                     float* __restrict__ C) {
    extern __shared__ char smem[];
    const uint32_t sb = smem_to_u32(smem);
    const int tid = threadIdx.x;
    const int bn = blockIdx.x << 7;
    const int bm = blockIdx.y << 7;
    const int wid = tid >> 5, lane = tid & 31;
    const int wm = (wid & 1) << 6;
    const int wn = (wid >> 1) << 5;
    const int lr = lane & 15;
    const int lhalf = lane >> 4;

    float acc[4][4][4];
#pragma unroll
    for (int i = 0; i < 4; i++)
#pragma unroll
        for (int j = 0; j < 4; j++)
#pragma unroll
            for (int k = 0; k < 4; k++) acc[i][j][k] = 0.f;

    load_stage(sb, Ahi, Alo, Bhi, Blo, bm, bn, 0, tid);
    CP_COMMIT();

    for (int s = 0; s < 32; s++) {
        CP_WAIT0();
        __syncthreads();
        if (s + 1 < 32) {
            load_stage(sb + ((s + 1) & 1) * STAGE_BYTES, Ahi, Alo, Bhi, Blo,
                       bm, bn, (s + 1) << 5, tid);
            CP_COMMIT();
        }

        const uint32_t buf = sb + (s & 1) * STAGE_BYTES;
#pragma unroll
        for (int kk = 0; kk < 2; kk++) {
            const int cb = (kk << 1) + lhalf;
            uint32_t a[4][4], b[2][4];
#pragma unroll
            for (int mi = 0; mi < 4; mi++)
                ldsm4(a[mi], buf + sw_off(wm + (mi << 4) + lr, cb));
#pragma unroll
            for (int np = 0; np < 2; np++)
                ldsm4(b[np], buf + 16384 + sw_off(wn + (np << 4) + lr, cb));
#pragma unroll
            for (int mi = 0; mi < 4; mi++) {
                mma16816(acc[mi][0], a[mi], b[0][0], b[0][2]);
                mma16816(acc[mi][1], a[mi], b[0][1], b[0][3]);
                mma16816(acc[mi][2], a[mi], b[1][0], b[1][2]);
                mma16816(acc[mi][3], a[mi], b[1][1], b[1][3]);
            }
            // Ahi x Blo
#pragma unroll
            for (int np = 0; np < 2; np++)
                ldsm4(b[np], buf + 24576 + sw_off(wn + (np << 4) + lr, cb));
#pragma unroll
            for (int mi = 0; mi < 4; mi++) {
                mma16816(acc[mi][0], a[mi], b[0][0], b[0][2]);
                mma16816(acc[mi][1], a[mi], b[0][1], b[0][3]);
                mma16816(acc[mi][2], a[mi], b[1][0], b[1][2]);
                mma16816(acc[mi][3], a[mi], b[1][1], b[1][3]);
            }
            // Alo x Bhi
#pragma unroll
            for (int mi = 0; mi < 4; mi++)
                ldsm4(a[mi], buf + 8192 + sw_off(wm + (mi << 4) + lr, cb));
#pragma unroll
            for (int np = 0; np < 2; np++)
                ldsm4(b[np], buf + 16384 + sw_off(wn + (np << 4) + lr, cb));
#pragma unroll
            for (int mi = 0; mi < 4; mi++) {
                mma16816(acc[mi][0], a[mi], b[0][0], b[0][2]);
                mma16816(acc[mi][1], a[mi], b[0][1], b[0][3]);
                mma16816(acc[mi][2], a[mi], b[1][0], b[1][2]);
                mma16816(acc[mi][3], a[mi], b[1][1], b[1][3]);
            }
        }
        __syncthreads();
    }

    const int crow = lane >> 2;
    const int ccol = (lane & 3) << 1;
#pragma unroll
    for (int ni = 0; ni < 4; ni++) {
        const int col = bn + wn + (ni << 3) + ccol;
        const float2 bv = *(const float2*)&bias[col];
#pragma unroll
        for (int mi = 0; mi < 4; mi++) {
            const int row = bm + wm + (mi << 4) + crow;
            float2 o0 = make_float2(acc[mi][ni][0] + bv.x, acc[mi][ni][1] + bv.y);
            float2 o1 = make_float2(acc[mi][ni][2] + bv.x, acc[mi][ni][3] + bv.y);
            *(float2*)&C[(size_t)row * DIMV + col] = o0;
            *(float2*)&C[(size_t)(row + 8) * DIMV + col] = o1;
        }
    }
}

// ---------------------------------------------------------------------------
// Fused RMSNorm + RoPE, writes bf16 hi/lo (scale folded in). 1 block/token.
// ---------------------------------------------------------------------------
__global__ __launch_bounds__(256) void normrope_split_kernel(
    const float* __restrict__ src, const float* __restrict__ g,
    const float* __restrict__ cs, const float* __restrict__ sn,
    __nv_bfloat16* __restrict__ hi, __nv_bfloat16* __restrict__ lo,
    float scale) {
    const int s = blockIdx.x;
    const int tid = threadIdx.x;

    float4 v = *(const float4*)&src[(size_t)s * DIMV + (tid << 2)];
    float ss = v.x * v.x + v.y * v.y + v.z * v.z + v.w * v.w;
#pragma unroll
    for (int o = 16; o; o >>= 1) ss += __shfl_xor_sync(0xffffffffu, ss, o);

    __shared__ float red[8];
    __shared__ float rtot;
    if ((tid & 31) == 0) red[tid >> 5] = ss;
    __syncthreads();
    if (tid == 0) {
        float t = 0.f;
#pragma unroll
        for (int i = 0; i < 8; i++) t += red[i];
        rtot = rsqrtf(t * (1.0f / 1024.0f) + 1e-6f);
    }
    __syncthreads();
    const float r = rtot;

    float4 gv = *(const float4*)&g[tid << 2];
    const float a0 = v.x * r * gv.x, b0 = v.y * r * gv.y;
    const float a1 = v.z * r * gv.z, b1 = v.w * r * gv.w;

    const int p0 = tid << 1;
    const int r0 = p0 & 31, r1 = (p0 + 1) & 31;
    const float c0 = cs[s * 32 + r0], s0 = sn[s * 32 + r0];
    const float c1 = cs[s * 32 + r1], s1 = sn[s * 32 + r1];

    float o0 = (a0 * c0 - b0 * s0) * scale;
    float o1 = (a0 * s0 + b0 * c0) * scale;
    float o2 = (a1 * c1 - b1 * s1) * scale;
    float o3 = (a1 * s1 + b1 * c1) * scale;

    B4 h, l;
    bsplit(o0, h.v[0], l.v[0]);
    bsplit(o1, h.v[1], l.v[1]);
    bsplit(o2, h.v[2], l.v[2]);
    bsplit(o3, h.v[3], l.v[3]);
    const size_t idx = (size_t)s * (DIMV / 4) + tid;
    ((B4*)hi)[idx] = h;
    ((B4*)lo)[idx] = l;
}

// ===========================================================================
// Tensor-core flash attention over dilated streams.
// Grid (68, 16, 2), 128 threads (4 warps), 64 queries/CTA, K/V tiles of 64.
// S = Qhi.Khi + Qlo.Khi + Qhi.Klo ; O = Phi.Vhi + Plo.Vhi + Phi.Vlo
// ===========================================================================
#define ATT_STAGE 32768
#define ATT_SMEM  (16384 + 2 * ATT_STAGE)

__global__ __launch_bounds__(128)
void attn_tc_kernel(const __nv_bfloat16* __restrict__ qhi, const __nv_bfloat16* __restrict__ qlo,
                    const __nv_bfloat16* __restrict__ khi, const __nv_bfloat16* __restrict__ klo,
                    const __nv_bfloat16* __restrict__ vhi, const __nv_bfloat16* __restrict__ vlo,
                    __nv_bfloat16* __restrict__ ohi, __nv_bfloat16* __restrict__ olo) {
    extern __shared__ char smem[];
    const uint32_t sb = smem_to_u32(smem);
    const int d = blockIdx.z, h = blockIdx.y;
    const int q0 = blockIdx.x << 6;
    const int tid = threadIdx.x;
    const int warp = tid >> 5, lane = tid & 31;
    const int wq = warp << 4;
    const int lr = lane & 15, lhf = lane >> 4;
    const int qr = lane >> 2, qc = (lane & 3) << 1;

    // --- load Q hi/lo tiles into smem (once) ---
#pragma unroll
    for (int t = 0; t < 4; t++) {
        const int idx = tid + (t << 7);
        const int r = idx >> 3, ch = idx & 7;
        const int tok = dil2orig(d, q0 + r);
        const size_t go = (size_t)tok * DIMV + h * HD + (ch << 3);
        *(uint4*)(smem + att_off(r, ch)) = *(const uint4*)&qhi[go];
        *(uint4*)(smem + 8192 + att_off(r, ch)) = *(const uint4*)&qlo[go];
    }
    __syncthreads();

    uint32_t qh[4][4], ql[4][4];
#pragma unroll
    for (int s = 0; s < 4; s++) {
        ldsm4(qh[s], sb + att_off(wq + lr, (s << 1) + lhf));
        ldsm4(ql[s], sb + 8192 + att_off(wq + lr, (s << 1) + lhf));
    }

    float m0 = -1e30f, m1 = -1e30f, l0 = 0.f, l1 = 0.f;
    float o[8][4];
#pragma unroll
    for (int j = 0; j < 8; j++)
#pragma unroll
        for (int k = 0; k < 4; k++) o[j][k] = 0.f;

    const int kt_lo = (q0 >= WIN) ? (q0 - WIN) : 0;
    const int kt_hi = min(SD, q0 + BQ + WIN);
    const int row0 = q0 + wq + qr, row1 = row0 + 8;

    // stage loader (K hi/lo + V hi/lo, zero-fill beyond SREAL)
    auto stage_load = [&](int st, int kt) {
        const uint32_t stg = sb + 16384 + st * ATT_STAGE;
#pragma unroll
        for (int t = 0; t < 16; t++) {
            const int cid = tid + (t << 7);
            const int buf = cid >> 9;
            const int idx = cid & 511;
            const int r = idx >> 3, ch = idx & 7;
            const int pk = kt + r;
            const int ok = pk < SREAL;
            const int tok = ok ? dil2orig(d, pk) : 0;
            const size_t go = (size_t)tok * DIMV + h * HD + (ch << 3);
            const __nv_bfloat16* src = (buf == 0) ? khi : (buf == 1) ? klo
                                      : (buf == 2) ? vhi : vlo;
            cp_async16z(stg + (buf << 13) + att_off(r, ch), src + go, ok ? 16 : 0);
        }
    };

    stage_load(0, kt_lo);
    CP_COMMIT();

    int st = 0;
    for (int kt = kt_lo; kt < kt_hi; kt += BK, st ^= 1) {
        CP_WAIT0();
        __syncthreads();
        if (kt + BK < kt_hi) { stage_load(st ^ 1, kt + BK); CP_COMMIT(); }

        const uint32_t sK  = sb + 16384 + st * ATT_STAGE;
        const uint32_t sKl = sK + 8192, sV = sK + 16384, sVl = sK + 24576;

        // --- scores ---
        float c[8][4];
#pragma unroll
        for (int j = 0; j < 8; j++)
#pragma unroll
            for (int k = 0; k < 4; k++) c[j][k] = 0.f;

#pragma unroll
        for (int s = 0; s < 4; s++) {
#pragma unroll
            for (int g = 0; g < 4; g++) {
                uint32_t bh[4], bl[4];
                ldsm4(bh, sK + att_off((g << 4) + lr, (s << 1) + lhf));
                ldsm4(bl, sKl + att_off((g << 4) + lr, (s << 1) + lhf));
                mma16816(c[2 * g],     qh[s], bh[0], bh[2]);
                mma16816(c[2 * g + 1], qh[s], bh[1], bh[3]);
                mma16816(c[2 * g],     ql[s], bh[0], bh[2]);
                mma16816(c[2 * g + 1], ql[s], bh[1], bh[3]);
                mma16816(c[2 * g],     qh[s], bl[0], bl[2]);
                mma16816(c[2 * g + 1], qh[s], bl[1], bl[3]);
            }
        }

        // --- window mask (edge tiles only) ---
        const bool edge = (kt < q0 - WIN + BK) || (kt >= q0 + WIN);
        if (edge) {
#pragma unroll
            for (int j = 0; j < 8; j++) {
                const int pk = kt + (j << 3) + qc;
                if (abs(row0 - pk) > WIN)       c[j][0] = -1e9f;
                if (abs(row0 - pk - 1) > WIN)   c[j][1] = -1e9f;
                if (abs(row1 - pk) > WIN)       c[j][2] = -1e9f;
                if (abs(row1 - pk - 1) > WIN)   c[j][3] = -1e9f;
            }
        }

        // --- online softmax ---
        float tm0 = -1e30f, tm1 = -1e30f;
#pragma unroll
        for (int j = 0; j < 8; j++) {
            tm0 = fmaxf(tm0, fmaxf(c[j][0], c[j][1]));
            tm1 = fmaxf(tm1, fmaxf(c[j][2], c[j][3]));
        }
        tm0 = fmaxf(tm0, __shfl_xor_sync(0xffffffffu, tm0, 1));
        tm0 = fmaxf(tm0, __shfl_xor_sync(0xffffffffu, tm0, 2));
        tm1 = fmaxf(tm1, __shfl_xor_sync(0xffffffffu, tm1, 1));
        tm1 = fmaxf(tm1, __shfl_xor_sync(0xffffffffu, tm1, 2));

        const float mn0 = fmaxf(m0, tm0), mn1 = fmaxf(m1, tm1);
        const float cor0 = __expf(m0 - mn0), cor1 = __expf(m1 - mn1);
        m0 = mn0; m1 = mn1;

        float s0 = 0.f, s1 = 0.f;
#pragma unroll
        for (int j = 0; j < 8; j++) {
            c[j][0] = __expf(c[j][0] - mn0);
            c[j][1] = __expf(c[j][1] - mn0);
            c[j][2] = __expf(c[j][2] - mn1);
            c[j][3] = __expf(c[j][3] - mn1);
            s0 += c[j][0] + c[j][1];
            s1 += c[j][2] + c[j][3];
        }
        s0 += __shfl_xor_sync(0xffffffffu, s0, 1);
        s0 += __shfl_xor_sync(0xffffffffu, s0, 2);
        s1 += __shfl_xor_sync(0xffffffffu, s1, 1);
        s1 += __shfl_xor_sync(0xffffffffu, s1, 2);
        l0 = l0 * cor0 + s0;
        l1 = l1 * cor1 + s1;
#pragma unroll
        for (int j = 0; j < 8; j++) {
            o[j][0] *= cor0; o[j][1] *= cor0;
            o[j][2] *= cor1; o[j][3] *= cor1;
        }

        // --- PV ---
#pragma unroll
        for (int s = 0; s < 4; s++) {
            // build P hi/lo A-fragments for key chunk [16s, 16s+16)
            uint32_t ah[4], al[4];
#pragma unroll
            for (int half = 0; half < 2; half++) {
                const int j = 2 * s + half;
                const float p0 = c[j][0], p1 = c[j][1];
                const float p2 = c[j][2], p3 = c[j][3];
                const float h0 = __bfloat162float(__float2bfloat16(p0));
                const float h1 = __bfloat162float(__float2bfloat16(p1));
                const float h2 = __bfloat162float(__float2bfloat16(p2));
                const float h3 = __bfloat162float(__float2bfloat16(p3));
                ah[2 * half]     = pack_bf16x2(h0, h1);
                ah[2 * half + 1] = pack_bf16x2(h2, h3);
                al[2 * half]     = pack_bf16x2(p0 - h0, p1 - h1);
                al[2 * half + 1] = pack_bf16x2(p2 - h2, p3 - h3);
            }
            // ah layout fix: A m16k16 frag order = {r0-7 klo, r8-15 klo, r0-7 khi, r8-15 khi}
            // built above as {lo: c01, c23}, {hi: c01, c23} -> need {c01lo, c23lo, c01hi, c23hi}
            // pack order: ah[0]=c01 of tile 2s, ah[1]=c23 of tile 2s, ah[2]=c01 of 2s+1, ah[3]=c23 of 2s+1  ✓
#pragma unroll
            for (int g = 0; g < 4; g++) {
                uint32_t bh[4], bl[4];
                ldsm4t(bh, sV + att_off((s << 4) + lr, (g << 1) + lhf));
                ldsm4t(bl, sVl + att_off((s << 4) + lr, (g << 1) + lhf));
                mma16816(o[2 * g],     ah, bh[0], bh[1]);
                mma16816(o[2 * g + 1], ah, bh[2], bh[3]);
                mma16816(o[2 * g],     al, bh[0], bh[1]);
                mma16816(o[2 * g + 1], al, bh[2], bh[3]);
                mma16816(o[2 * g],     ah, bl[0], bl[1]);
                mma16816(o[2 * g + 1], ah, bl[2], bl[3]);
            }
        }
        __syncthreads();
    }

    // --- epilogue: normalize, split to bf16 hi/lo, store ---
    const float inv0 = 1.0f / l0, inv1 = 1.0f / l1;
    const int tok0 = dil2orig(d, row0);
    const int tok1 = dil2orig(d, row1);
#pragma unroll
    for (int j = 0; j < 8; j++) {
        const int col = h * HD + (j << 3) + qc;
        const float a0 = o[j][0] * inv0, a1 = o[j][1] * inv0;
        const float b0 = o[j][2] * inv1, b1 = o[j][3] * inv1;
        const float a0h = __bfloat162float(__float2bfloat16(a0));
        const float a1h = __bfloat162float(__float2bfloat16(a1));
        const float b0h = __bfloat162float(__float2bfloat16(b0));
        const float b1h = __bfloat162float(__float2bfloat16(b1));
        *(uint32_t*)&ohi[(size_t)tok0 * DIMV + col] = pack_bf16x2(a0h, a1h);
        *(uint32_t*)&olo[(size_t)tok0 * DIMV + col] = pack_bf16x2(a0 - a0h, a1 - a1h);
        *(uint32_t*)&ohi[(size_t)tok1 * DIMV + col] = pack_bf16x2(b0h, b1h);
        *(uint32_t*)&olo[(size_t)tok1 * DIMV + col] = pack_bf16x2(b0 - b0h, b1 - b1h);
    }
}

// ---------------------------------------------------------------------------
extern "C" void kernel_launch(void* const* d_in, const int* in_sizes, int n_in,
                              void* d_out, int out_size) {
    (void)in_sizes; (void)n_in; (void)out_size;
    const float* x  = (const float*)d_in[0];
    const float* fc = (const float*)d_in[1];
    const float* fs = (const float*)d_in[2];
    const float* wq = (const float*)d_in[3];
    const float* bq = (const float*)d_in[4];
    const float* wk = (const float*)d_in[5];
    const float* bk = (const float*)d_in[6];
    const float* wv = (const float*)d_in[7];
    const float* bv = (const float*)d_in[8];
    const float* wo = (const float*)d_in[9];
    const float* bo = (const float*)d_in[10];
    const float* gq = (const float*)d_in[11];
    const float* gk = (const float*)d_in[12];
    float* out = (float*)d_out;

    float *qb, *kb, *vb;
    cudaGetSymbolAddress((void**)&qb, g_q);
    cudaGetSymbolAddress((void**)&kb, g_k);
    cudaGetSymbolAddress((void**)&vb, g_v);
    __nv_bfloat16 *ahi, *alo, *qhi, *qlo, *khi, *klo, *vhi, *vlo;
    cudaGetSymbolAddress((void**)&ahi, g_ahi);
    cudaGetSymbolAddress((void**)&alo, g_alo);
    cudaGetSymbolAddress((void**)&qhi, g_qhi);
    cudaGetSymbolAddress((void**)&qlo, g_qlo);
    cudaGetSymbolAddress((void**)&khi, g_khi);
    cudaGetSymbolAddress((void**)&klo, g_klo);
    cudaGetSymbolAddress((void**)&vhi, g_vhi);
    cudaGetSymbolAddress((void**)&vlo, g_vlo);
    __nv_bfloat16 *wqh, *wql, *wkh, *wkl, *wvh, *wvl, *woh, *wol;
    cudaGetSymbolAddress((void**)&wqh, g_wqT_hi);
    cudaGetSymbolAddress((void**)&wql, g_wqT_lo);
    cudaGetSymbolAddress((void**)&wkh, g_wkT_hi);
    cudaGetSymbolAddress((void**)&wkl, g_wkT_lo);
    cudaGetSymbolAddress((void**)&wvh, g_wvT_hi);
    cudaGetSymbolAddress((void**)&wvl, g_wvT_lo);
    cudaGetSymbolAddress((void**)&woh, g_woT_hi);
    cudaGetSymbolAddress((void**)&wol, g_woT_lo);

    cudaFuncSetAttribute(gemm_mma_kernel,
                         cudaFuncAttributeMaxDynamicSharedMemorySize, GEMM_SMEM_REQ);
    cudaFuncSetAttribute(attn_tc_kernel,
                         cudaFuncAttributeMaxDynamicSharedMemorySize, ATT_SMEM);

    const dim3 wgrid(32, 32);
    const dim3 wblk(32, 8);
    wsplit_kernel<<<wgrid, wblk>>>(wq, wqh, wql);
    wsplit_kernel<<<wgrid, wblk>>>(wk, wkh, wkl);
    wsplit_kernel<<<wgrid, wblk>>>(wv, wvh, wvl);
    wsplit_kernel<<<wgrid, wblk>>>(wo, woh, wol);

    split_kernel<<<(S_LEN * DIMV) / 1024, 256>>>(x, ahi, alo);

    const dim3 ggrid(DIMV / 128, S_LEN / 128);
    gemm_mma_kernel<<<ggrid, 256, GEMM_SMEM_REQ>>>(ahi, alo, wqh, wql, bq, qb);
    gemm_mma_kernel<<<ggrid, 256, GEMM_SMEM_REQ>>>(ahi, alo, wkh, wkl, bk, kb);
    gemm_mma_kernel<<<ggrid, 256, GEMM_SMEM_REQ>>>(ahi, alo, wvh, wvl, bv, vb);

    normrope_split_kernel<<<S_LEN, 256>>>(qb, gq, fc, fs, qhi, qlo, 0.125f);
    normrope_split_kernel<<<S_LEN, 256>>>(kb, gk, fc, fs, khi, klo, 1.0f);
    split_kernel<<<(S_LEN * DIMV) / 1024, 256>>>(vb, vhi, vlo);

    attn_tc_kernel<<<dim3(SREAL / BQ, NH, 2), 128, ATT_SMEM>>>(
        qhi, qlo, khi, klo, vhi, vlo, ahi, alo);

    gemm_mma_kernel<<<ggrid, 256, GEMM_SMEM_REQ>>>(ahi, alo, woh, wol, bo, out);
}